// round 12
// baseline (speedup 1.0000x reference)
#include <cuda_runtime.h>

#define B_EX   16384
#define NEG    10
#define NVAL   (NEG + 1)      // 11 partial values per example (pos + 10 neg)
#define WARPS_PER_BLOCK 4
#define THREADS (WARPS_PER_BLOCK * 32)     // 128
#define NBLOCKS (B_EX / WARPS_PER_BLOCK)   // 4096
#define NLOSS   (WARPS_PER_BLOCK * NVAL)   // 44 loss terms per block

// Scratch (allocation-free __device__ globals per harness rules)
__device__ float        g_partials[NBLOCKS];
__device__ unsigned int g_count = 0;

__device__ __forceinline__ float log_sigmoid(float x) {
    return fminf(x, 0.0f) - log1pf(expf(-fabsf(x)));
}

__device__ __forceinline__ float dot4(float4 a, float4 b) {
    return a.x * b.x + a.y * b.y + a.z * b.z + a.w * b.w;
}

__global__ void __launch_bounds__(THREADS)
w2v_fused_kernel(const int*    __restrict__ input_word,
                 const int*    __restrict__ context_word,
                 const int*    __restrict__ noise_words,
                 const float4* __restrict__ W_in,
                 const float4* __restrict__ W_ctx,
                 float*        __restrict__ out)
{
    // Per-lane partials, padded to 33 floats so the transposed read
    // (fixed j, thread-varying row) is bank-conflict-free.
    __shared__ float sp[WARPS_PER_BLOCK][NVAL][33];   // 5.8 KB
    __shared__ float s_vals[NLOSS];                   // 44 loss terms
    __shared__ bool  s_is_last;

    const int lane    = threadIdx.x & 31;
    const int warp_in = threadIdx.x >> 5;
    const int b       = blockIdx.x * WARPS_PER_BLOCK + warp_in;   // example id

    // Uniform (same-address) index loads: L1-broadcast within the warp.
    const int ci = input_word[b];
    const int xi = context_word[b];
    int nidx[NEG];
#pragma unroll
    for (int k = 0; k < NEG; k++) nidx[k] = noise_words[b * NEG + k];

    // Row = 128 floats = 32 float4; lane l owns float4 #l of each row.
    // All 12 gathers issued before any math.
    float4 c = W_in [(size_t)ci * 32 + lane];
    float4 x = W_ctx[(size_t)xi * 32 + lane];
    float4 nv[NEG];
#pragma unroll
    for (int k = 0; k < NEG; k++)
        nv[k] = W_ctx[(size_t)nidx[k] * 32 + lane];

    // Per-lane partial dots -> smem (no shuffle butterflies).
    sp[warp_in][0][lane] = dot4(c, x);
#pragma unroll
    for (int k = 0; k < NEG; k++)
        sp[warp_in][1 + k][lane] = dot4(c, nv[k]);
    __syncthreads();

    // 44 threads: each sums one (example, k) column of 32 partials
    // (fixed-order serial sum -> deterministic) and applies log-sigmoid.
    const int t = threadIdx.x;
    if (t < NLOSS) {
        const int ex = t / NVAL;
        const int k  = t % NVAL;
        float s = 0.0f;
#pragma unroll
        for (int j = 0; j < 32; j++)
            s += sp[ex][k][j];
        s_vals[t] = (k == 0) ? -log_sigmoid(s) : -log_sigmoid(-s);
    }
    __syncthreads();

    // Warp 0 reduces the 44 loss terms (fixed order: deterministic).
    if (warp_in == 0) {
        float v = 0.0f;
#pragma unroll
        for (int j = 0; j < 2; j++) {
            int idx = lane + j * 32;
            if (idx < NLOSS) v += s_vals[idx];
        }
#pragma unroll
        for (int off = 16; off > 0; off >>= 1)
            v += __shfl_xor_sync(0xffffffffu, v, off);

        if (lane == 0) {
            g_partials[blockIdx.x] = v;
            unsigned int cnt;
            asm volatile("atom.release.gpu.global.add.u32 %0, [%1], 1;"
                         : "=r"(cnt) : "l"(&g_count) : "memory");
            s_is_last = (cnt == (unsigned int)(NBLOCKS - 1));
        }
    }
    __syncthreads();

    // ---- fused finalize: last block reduces all block partials ----
    if (s_is_last) {
        asm volatile("fence.acquire.gpu;" ::: "memory");
        volatile float* gp = g_partials;
        float tacc = 0.0f;
#pragma unroll
        for (int j = 0; j < NBLOCKS / THREADS; j++)     // 32 iterations
            tacc += gp[threadIdx.x + j * THREADS];

        __shared__ float s_red[THREADS];
        s_red[threadIdx.x] = tacc;
        __syncthreads();
#pragma unroll
        for (int step = THREADS / 2; step > 0; step >>= 1) {
            if (threadIdx.x < step) s_red[threadIdx.x] += s_red[threadIdx.x + step];
            __syncthreads();
        }
        if (threadIdx.x == 0) {
            out[0]  = s_red[0] / (float)B_EX;
            g_count = 0;                   // reset for next graph replay
        }
    }
}

extern "C" void kernel_launch(void* const* d_in, const int* in_sizes, int n_in,
                              void* d_out, int out_size)
{
    const int*    input_word   = (const int*)   d_in[0];
    const int*    context_word = (const int*)   d_in[1];
    const int*    noise_words  = (const int*)   d_in[2];
    const float4* W_in         = (const float4*)d_in[3];
    const float4* W_ctx        = (const float4*)d_in[4];
    float* out = (float*)d_out;

    w2v_fused_kernel<<<NBLOCKS, THREADS>>>(input_word, context_word,
                                           noise_words, W_in, W_ctx, out);
}

// round 13
// speedup vs baseline: 1.1186x; 1.1186x over previous
#include <cuda_runtime.h>

#define B_EX   16384
#define NEG    10
#define NVAL   (NEG + 1)      // 11 partial values per example (pos + 10 neg)
#define WARPS_PER_BLOCK 8
#define THREADS (WARPS_PER_BLOCK * 32)
#define NBLOCKS (B_EX / WARPS_PER_BLOCK)   // 2048
#define NLOSS   (WARPS_PER_BLOCK * NVAL)   // 88 loss terms per block

// Scratch (allocation-free __device__ globals per harness rules)
__device__ float        g_partials[NBLOCKS];
__device__ unsigned int g_count = 0;

__device__ __forceinline__ float log_sigmoid(float x) {
    return fminf(x, 0.0f) - log1pf(expf(-fabsf(x)));
}

__device__ __forceinline__ float dot4(float4 a, float4 b) {
    return a.x * b.x + a.y * b.y + a.z * b.z + a.w * b.w;
}

__global__ void __launch_bounds__(THREADS)
w2v_fused_kernel(const int*    __restrict__ input_word,
                 const int*    __restrict__ context_word,
                 const int*    __restrict__ noise_words,
                 const float4* __restrict__ W_in,
                 const float4* __restrict__ W_ctx,
                 float*        __restrict__ out)
{
    // Per-lane partials, padded to 33 floats so the transposed read
    // (fixed j, thread-varying row) is bank-conflict-free.
    __shared__ float sp[WARPS_PER_BLOCK][NVAL][33];   // 11.6 KB
    __shared__ float s_vals[NLOSS];                   // 88 loss terms
    __shared__ bool  s_is_last;

    const int lane    = threadIdx.x & 31;
    const int warp_in = threadIdx.x >> 5;
    const int b       = blockIdx.x * WARPS_PER_BLOCK + warp_in;   // example id

    // Noise indices FIRST (they gate 10 of 12 gathers), vectorized int2:
    // noise_words + b*10 is 8-byte aligned for every b.
    const int2* np = (const int2*)(noise_words + b * NEG);
    int2 np0 = np[0], np1 = np[1], np2 = np[2], np3 = np[3], np4 = np[4];
    const int ci = input_word[b];
    const int xi = context_word[b];
    const int nidx[NEG] = { np0.x, np0.y, np1.x, np1.y, np2.x,
                            np2.y, np3.x, np3.y, np4.x, np4.y };

    // Row = 128 floats = 32 float4; lane l owns float4 #l of each row.
    // All 12 gathers issued before any math.
    float4 nv[NEG];
#pragma unroll
    for (int k = 0; k < NEG; k++)
        nv[k] = W_ctx[(size_t)nidx[k] * 32 + lane];
    float4 c = W_in [(size_t)ci * 32 + lane];
    float4 x = W_ctx[(size_t)xi * 32 + lane];

    // Per-lane partial dots -> smem (no shuffle butterflies).
    sp[warp_in][0][lane] = dot4(c, x);
#pragma unroll
    for (int k = 0; k < NEG; k++)
        sp[warp_in][1 + k][lane] = dot4(c, nv[k]);
    __syncthreads();

    // 88 threads: each sums one (example, k) column of 32 partials
    // (fixed-order serial sum -> deterministic) and applies log-sigmoid.
    const int t = threadIdx.x;
    if (t < NLOSS) {
        const int ex = t / NVAL;
        const int k  = t % NVAL;
        float s = 0.0f;
#pragma unroll
        for (int j = 0; j < 32; j++)
            s += sp[ex][k][j];
        s_vals[t] = (k == 0) ? -log_sigmoid(s) : -log_sigmoid(-s);
    }
    __syncthreads();

    // Warp 0 reduces the 88 loss terms (fixed order: deterministic).
    if (warp_in == 0) {
        float v = 0.0f;
#pragma unroll
        for (int j = 0; j < 3; j++) {
            int idx = lane + j * 32;
            if (idx < NLOSS) v += s_vals[idx];
        }
#pragma unroll
        for (int off = 16; off > 0; off >>= 1)
            v += __shfl_xor_sync(0xffffffffu, v, off);

        if (lane == 0) {
            g_partials[blockIdx.x] = v;
            unsigned int cnt;
            asm volatile("atom.release.gpu.global.add.u32 %0, [%1], 1;"
                         : "=r"(cnt) : "l"(&g_count) : "memory");
            s_is_last = (cnt == (unsigned int)(NBLOCKS - 1));
        }
    }
    __syncthreads();

    // ---- fused finalize: last block reduces all block partials ----
    if (s_is_last) {
        asm volatile("fence.acquire.gpu;" ::: "memory");
        volatile float* gp = g_partials;
        float tacc = 0.0f;
#pragma unroll
        for (int j = 0; j < NBLOCKS / THREADS; j++)     // 8 iterations
            tacc += gp[threadIdx.x + j * THREADS];

        __shared__ float s_red[THREADS];
        s_red[threadIdx.x] = tacc;
        __syncthreads();
#pragma unroll
        for (int step = THREADS / 2; step > 0; step >>= 1) {
            if (threadIdx.x < step) s_red[threadIdx.x] += s_red[threadIdx.x + step];
            __syncthreads();
        }
        if (threadIdx.x == 0) {
            out[0]  = s_red[0] / (float)B_EX;
            g_count = 0;                   // reset for next graph replay
        }
    }
}

extern "C" void kernel_launch(void* const* d_in, const int* in_sizes, int n_in,
                              void* d_out, int out_size)
{
    const int*    input_word   = (const int*)   d_in[0];
    const int*    context_word = (const int*)   d_in[1];
    const int*    noise_words  = (const int*)   d_in[2];
    const float4* W_in         = (const float4*)d_in[3];
    const float4* W_ctx        = (const float4*)d_in[4];
    float* out = (float*)d_out;

    w2v_fused_kernel<<<NBLOCKS, THREADS>>>(input_word, context_word,
                                           noise_words, W_in, W_ctx, out);
}